// round 17
// baseline (speedup 1.0000x reference)
#include <cuda_runtime.h>
#include <cstdint>

#define NB 8192
#define NPARAM 4849
#define NPPAD 4864     // padded N (38*128)
#define PPAD 4864      // param row stride
#define NH 96
#define KSP 288        // term-major split K: A=[ah|ah|al], B=[bh|bl|bh]
#define NSTEPS 20

// Device-global scratch (allocation-free per harness rules)
__device__ float g_params[(size_t)NB * PPAD];     // 159 MB
__device__ float g_A[(size_t)NB * KSP];           // 9.4 MB
__device__ float g_B[(size_t)NPPAD * KSP];        // 5.6 MB

__device__ __forceinline__ float sigmoidf(float z) {
    return 1.0f / (1.0f + __expf(-z));
}
__device__ __forceinline__ float tf32_rn(float v) {
    uint32_t t;
    asm("cvt.rna.tf32.f32 %0, %1;" : "=r"(t) : "f"(v));
    return __uint_as_float(t);
}
__device__ __forceinline__ uint32_t smem_u32(const void* p) {
    uint32_t a;
    asm("{ .reg .u64 t; cvta.to.shared.u64 t, %1; cvt.u32.u64 %0, t; }" : "=r"(a) : "l"(p));
    return a;
}
__device__ __forceinline__ void cpa16(uint32_t dst, const void* src) {
    asm volatile("cp.async.ca.shared.global [%0], [%1], 16;" :: "r"(dst), "l"(src));
}

// ---------------------------------------------------------------------------
// Merged prep: range A = hyper hidden + tf32 split [ah|ah|al];
//              range B = tf32 split of hw2 rows [bh|bl|bh]
// ---------------------------------------------------------------------------
#define NPREP_A (NB * NH)
#define NPREP_B (NPPAD * NH)

__global__ void prep_kernel(const float* __restrict__ x, const float* __restrict__ c,
                            const float* __restrict__ hw1, const float* __restrict__ hb1,
                            const float* __restrict__ hw2) {
    int idx = blockIdx.x * blockDim.x + threadIdx.x;
    if (idx < NPREP_A) {
        int b = idx / NH;
        int k = idx - b * NH;
        float v = fmaf(hw1[2 * k], x[b], fmaf(hw1[2 * k + 1], c[b], hb1[k]));
        v = fmaxf(v, 0.0f);
        float hi = tf32_rn(v);
        float lo = tf32_rn(v - hi);
        size_t base = (size_t)b * KSP;
        g_A[base + k]       = hi;
        g_A[base + 96 + k]  = hi;
        g_A[base + 192 + k] = lo;
    } else if (idx < NPREP_A + NPREP_B) {
        int r = idx - NPREP_A;
        int j = r / NH;
        int k = r - j * NH;
        float w = (j < NPARAM) ? hw2[j * NH + k] : 0.0f;
        float hi = tf32_rn(w);
        float lo = tf32_rn(w - hi);
        size_t base = (size_t)j * KSP;
        g_B[base + k]       = hi;
        g_B[base + 96 + k]  = lo;
        g_B[base + 192 + k] = hi;
    }
}

// ---------------------------------------------------------------------------
// 3xTF32 GEMM, cp.async double-buffered (unchanged from R16).
// ---------------------------------------------------------------------------
#define CHK 48
#define SP 52
#define STAGEF (2 * 128 * SP)
#define GT_SMEM (2 * STAGEF * 4)                // 106496 bytes

__device__ __forceinline__ void mma1688_tf32(float* c, const uint32_t* a, const uint32_t* b) {
    asm volatile(
        "mma.sync.aligned.m16n8k8.row.col.f32.tf32.tf32.f32 "
        "{%0,%1,%2,%3}, {%4,%5,%6,%7}, {%8,%9}, {%0,%1,%2,%3};"
        : "+f"(c[0]), "+f"(c[1]), "+f"(c[2]), "+f"(c[3])
        : "r"(a[0]), "r"(a[1]), "r"(a[2]), "r"(a[3]), "r"(b[0]), "r"(b[1]));
}

__global__ __launch_bounds__(256, 2) void gemm_mma_kernel(const float* __restrict__ hb2) {
    extern __shared__ __align__(16) float sm[];

    const int tid = threadIdx.x;
    const int wid = tid >> 5;
    const int lid = tid & 31;
    const int b0 = blockIdx.x * 128;
    const int j0 = blockIdx.y * 128;

    auto load_chunk = [&](int c, int st) {
        float* As = sm + st * STAGEF;
        float* Bs = As + 128 * SP;
#pragma unroll
        for (int l = 0; l < 6; l++) {
            int idx = tid + l * 256;
            int m = idx / 12;
            int seg = idx - m * 12;
            cpa16(smem_u32(As + m * SP + seg * 4),
                  g_A + (size_t)(b0 + m) * KSP + c * CHK + seg * 4);
            cpa16(smem_u32(Bs + m * SP + seg * 4),
                  g_B + (size_t)(j0 + m) * KSP + c * CHK + seg * 4);
        }
        asm volatile("cp.async.commit_group;" ::: "memory");
    };

    const int wm = (wid & 3) * 32;
    const int wn = (wid >> 2) * 64;
    const int grp = lid >> 2;
    const int tig = lid & 3;

    float acc[2][8][4];
#pragma unroll
    for (int mi = 0; mi < 2; mi++)
#pragma unroll
        for (int ni = 0; ni < 8; ni++)
#pragma unroll
            for (int q = 0; q < 4; q++) acc[mi][ni][q] = 0.0f;

    load_chunk(0, 0);

#pragma unroll 1
    for (int c = 0; c < 6; c++) {
        if (c < 5) {
            load_chunk(c + 1, (c + 1) & 1);
            asm volatile("cp.async.wait_group 1;" ::: "memory");
        } else {
            asm volatile("cp.async.wait_group 0;" ::: "memory");
        }
        __syncthreads();

        const float* As = sm + (c & 1) * STAGEF;
        const float* Bs = As + 128 * SP;
#pragma unroll
        for (int ks = 0; ks < 6; ks++) {
            const int k = ks * 8 + tig;
            uint32_t a[2][4];
#pragma unroll
            for (int mi = 0; mi < 2; mi++) {
                int r = wm + mi * 16 + grp;
                a[mi][0] = *(const uint32_t*)(As + r * SP + k);
                a[mi][1] = *(const uint32_t*)(As + (r + 8) * SP + k);
                a[mi][2] = *(const uint32_t*)(As + r * SP + k + 4);
                a[mi][3] = *(const uint32_t*)(As + (r + 8) * SP + k + 4);
            }
            uint32_t b[8][2];
#pragma unroll
            for (int ni = 0; ni < 8; ni++) {
                int n = wn + ni * 8 + grp;
                b[ni][0] = *(const uint32_t*)(Bs + n * SP + k);
                b[ni][1] = *(const uint32_t*)(Bs + n * SP + k + 4);
            }
#pragma unroll
            for (int mi = 0; mi < 2; mi++)
#pragma unroll
                for (int ni = 0; ni < 8; ni++)
                    mma1688_tf32(acc[mi][ni], a[mi], b[ni]);
        }
        __syncthreads();
    }

#pragma unroll
    for (int ni = 0; ni < 8; ni++) {
        const int col = j0 + wn + ni * 8 + 2 * tig;
        const float bx = (col < NPARAM) ? hb2[col] : 0.0f;
        const float by = (col + 1 < NPARAM) ? hb2[col + 1] : 0.0f;
#pragma unroll
        for (int mi = 0; mi < 2; mi++) {
            const int r0 = b0 + wm + mi * 16 + grp;
            *(float2*)(g_params + (size_t)r0 * PPAD + col) =
                make_float2(acc[mi][ni][0] + bx, acc[mi][ni][1] + by);
            *(float2*)(g_params + (size_t)(r0 + 8) * PPAD + col) =
                make_float2(acc[mi][ni][2] + bx, acc[mi][ni][3] + by);
        }
    }
}

// ---------------------------------------------------------------------------
// Adam loop v3: w1 in registers, w2 in SMEM (transposed, conflict-free) to
// cut regs ~159 -> ~85 and double occupancy (4 blocks/SM, 24 warps).
// 48 threads/sample, 4 samples/block.  Split accumulators (8 chains).
// ---------------------------------------------------------------------------
#define SPB 4
#define SLAB 2352   // 48*49 floats; 2352 % 32 == 16 -> mixed-sample warps conflict-free

__global__ __launch_bounds__(48 * SPB, 4) void adam_kernel(float* __restrict__ out) {
    __shared__ float w2T[SPB * SLAB];                 // 36.75 KB
    __shared__ __align__(16) float h0s[SPB][48];
    __shared__ __align__(16) float dh0s[SPB][48];
    __shared__ __align__(16) float h1s[SPB][48];
    __shared__ __align__(16) float dh1s[SPB][48];
    __shared__ __align__(16) float part[SPB][48];

    const int tid = threadIdx.x;
    const int s = tid / 48;
    const int i = tid - s * 48;
    const int sample = blockIdx.x * SPB + s;

    const float* p = g_params + (size_t)sample * PPAD;

    // Layout: w0[48] b0[48] w1[48x48] b1[48] w2[48x48] b2[48] w3[48] b3
    const float w0i = p[i];
    const float b0i = p[48 + i];
    const float b1i = p[2400 + i];
    const float b2i = p[4752 + i];
    const float w3i = p[4800 + i];

    // w1 row -> registers
    float w1r[48];
    {
        const float4* p1 = (const float4*)(p + 96 + i * 48);
#pragma unroll
        for (int q = 0; q < 12; q++) {
            float4 a = p1[q];
            w1r[4 * q + 0] = a.x; w1r[4 * q + 1] = a.y; w1r[4 * q + 2] = a.z; w1r[4 * q + 3] = a.w;
        }
    }
    // w2 row -> SMEM transposed: w2T[s*SLAB + k*49 + i] = w2[i][k]
    {
        const float4* p2 = (const float4*)(p + 2448 + i * 48);
        float* wc = w2T + s * SLAB + i;
#pragma unroll
        for (int q = 0; q < 12; q++) {
            float4 b = p2[q];
            wc[(4 * q + 0) * 49] = b.x;
            wc[(4 * q + 1) * 49] = b.y;
            wc[(4 * q + 2) * 49] = b.z;
            wc[(4 * q + 3) * 49] = b.w;
        }
    }
    __syncthreads();

    const float* wc = w2T + s * SLAB + i;   // column i of sample s

    float y = 0.0f, mA = 0.0f, vA = 0.0f, pb1 = 1.0f, pb2 = 1.0f;

#pragma unroll 1
    for (int t = 0; t < NSTEPS; t++) {
        // Layer 0 (scalar input): z0 = w0*y + b0 ; tangent dz0 = w0
        float z0 = fmaf(w0i, y, b0i);
        float s0 = sigmoidf(z0);
        h0s[s][i]  = z0 * s0;
        dh0s[s][i] = (s0 + z0 * s0 * (1.0f - s0)) * w0i;
        __syncthreads();

        // Layer 1: w1 from regs, 8 independent FMA chains
        float a0 = b1i, a1 = 0.0f, a2 = 0.0f, a3 = 0.0f;
        float d0 = 0.0f, d1 = 0.0f, d2 = 0.0f, d3 = 0.0f;
        {
            const float4* h4 = (const float4*)h0s[s];
            const float4* d4 = (const float4*)dh0s[s];
#pragma unroll
            for (int q = 0; q < 12; q++) {
                float4 hv = h4[q], dv = d4[q];
                a0 = fmaf(w1r[4 * q + 0], hv.x, a0);
                a1 = fmaf(w1r[4 * q + 1], hv.y, a1);
                a2 = fmaf(w1r[4 * q + 2], hv.z, a2);
                a3 = fmaf(w1r[4 * q + 3], hv.w, a3);
                d0 = fmaf(w1r[4 * q + 0], dv.x, d0);
                d1 = fmaf(w1r[4 * q + 1], dv.y, d1);
                d2 = fmaf(w1r[4 * q + 2], dv.z, d2);
                d3 = fmaf(w1r[4 * q + 3], dv.w, d3);
            }
        }
        float acc  = (a0 + a1) + (a2 + a3);
        float dacc = (d0 + d1) + (d2 + d3);

        float s1 = sigmoidf(acc);
        h1s[s][i]  = acc * s1;
        dh1s[s][i] = (s1 + acc * s1 * (1.0f - s1)) * dacc;
        __syncthreads();

        // Layer 2: w2 from SMEM (conflict-free column reads, immediate offsets)
        a0 = b2i; a1 = 0.0f; a2 = 0.0f; a3 = 0.0f;
        d0 = 0.0f; d1 = 0.0f; d2 = 0.0f; d3 = 0.0f;
        {
            const float4* h4 = (const float4*)h1s[s];
            const float4* d4 = (const float4*)dh1s[s];
#pragma unroll
            for (int q = 0; q < 12; q++) {
                float4 hv = h4[q], dv = d4[q];
                float wk0 = wc[(4 * q + 0) * 49];
                float wk1 = wc[(4 * q + 1) * 49];
                float wk2 = wc[(4 * q + 2) * 49];
                float wk3 = wc[(4 * q + 3) * 49];
                a0 = fmaf(wk0, hv.x, a0);
                a1 = fmaf(wk1, hv.y, a1);
                a2 = fmaf(wk2, hv.z, a2);
                a3 = fmaf(wk3, hv.w, a3);
                d0 = fmaf(wk0, dv.x, d0);
                d1 = fmaf(wk1, dv.y, d1);
                d2 = fmaf(wk2, dv.z, d2);
                d3 = fmaf(wk3, dv.w, d3);
            }
        }
        acc  = (a0 + a1) + (a2 + a3);
        dacc = (d0 + d1) + (d2 + d3);

        float s2 = sigmoidf(acc);
        // output-layer tangent contribution (b3 drops out of the gradient)
        part[s][i] = w3i * ((s2 + acc * s2 * (1.0f - s2)) * dacc);
        __syncthreads();

        // g = sum_i part_i  (redundant in all threads: deterministic)
        float g0 = 0.0f, g1 = 0.0f, g2 = 0.0f, g3 = 0.0f;
        {
            const float4* q4 = (const float4*)part[s];
#pragma unroll
            for (int q = 0; q < 12; q++) {
                float4 pv = q4[q];
                g0 += pv.x; g1 += pv.y; g2 += pv.z; g3 += pv.w;
            }
        }
        float g = (g0 + g1) + (g2 + g3);

        // Adam update
        pb1 *= 0.9f;
        pb2 *= 0.999f;
        mA = 0.9f * mA + 0.1f * g;
        vA = 0.999f * vA + 0.001f * g * g;
        float mh = mA / (1.0f - pb1);
        float vh = vA / (1.0f - pb2);
        y -= 0.1f * mh / (sqrtf(vh) + 1e-8f);
    }

    if (i == 0) out[sample] = y;
}

// ---------------------------------------------------------------------------
extern "C" void kernel_launch(void* const* d_in, const int* in_sizes, int n_in,
                              void* d_out, int out_size) {
    const float* x   = (const float*)d_in[0];   // (8192,1)
    const float* c   = (const float*)d_in[1];   // (8192,1)
    const float* hw1 = (const float*)d_in[2];   // (96,2)
    const float* hb1 = (const float*)d_in[3];   // (96,)
    const float* hw2 = (const float*)d_in[4];   // (4849,96)
    const float* hb2 = (const float*)d_in[5];   // (4849,)
    float* out = (float*)d_out;                 // (8192,1)

    (void)in_sizes; (void)n_in; (void)out_size;

    cudaFuncSetAttribute(gemm_mma_kernel,
                         cudaFuncAttributeMaxDynamicSharedMemorySize, GT_SMEM);

    prep_kernel<<<(NPREP_A + NPREP_B + 255) / 256, 256>>>(x, c, hw1, hb1, hw2);

    dim3 grid(NB / 128, NPPAD / 128);           // (64, 38)
    gemm_mma_kernel<<<grid, 256, GT_SMEM>>>(hb2);

    adam_kernel<<<NB / SPB, 48 * SPB>>>(out);
}